// round 4
// baseline (speedup 1.0000x reference)
#include <cuda_runtime.h>
#include <cuda_bf16.h>
#include <cstdint>
#include <cstddef>

#define BB 256
#define TT 2048
#define II 64
#define HH 256
#define OO 64
#define FF 16
#define NB 4   // batches per cluster in the recurrence kernel

// 512 MB scratch, reused in place: pre0 -> ys0 -> pre1 -> ys1. Layout [t][b][h].
__device__ float g_buf[(size_t)TT * BB * HH];

// ---------------------------------------------------------------------------
// K1: pre0[t,b,n] = x[b,t,:] . W_ih0[n,:] + b_ih0[n] + b_hh0[n]
// M = T*B (m = t*256+b), K = 64, N = 256. 64x256 tile, 256 threads, 8x8/thread.
// ---------------------------------------------------------------------------
__global__ void __launch_bounds__(256)
pre0_kernel(const float* __restrict__ x, const float* __restrict__ Wih,
            const float* __restrict__ bih, const float* __restrict__ bhh) {
    extern __shared__ float sm[];
    float* As = sm;             // [64 k][65 pad] (A transposed: k-major)
    float* Bs = sm + 64 * 65;   // [64 k][257 pad]
    const int tid = threadIdx.x;
    const int m0 = blockIdx.x * 64;

    for (int e = tid; e < 64 * 64; e += 256) {
        int r = e >> 6, k = e & 63;
        int m = m0 + r;
        int b = m & (BB - 1);
        int t = m >> 8;
        As[k * 65 + r] = x[((size_t)b * TT + t) * II + k];
    }
    for (int e = tid; e < 64 * 256; e += 256) {
        int n = e >> 6, k = e & 63;
        Bs[k * 257 + n] = Wih[n * II + k];
    }
    __syncthreads();

    const int tm = tid & 7;
    const int tn = tid >> 3;
    float acc[8][8];
#pragma unroll
    for (int i = 0; i < 8; i++)
#pragma unroll
        for (int j = 0; j < 8; j++) acc[i][j] = 0.f;

#pragma unroll 8
    for (int k = 0; k < 64; k++) {
        float a[8], bv[8];
#pragma unroll
        for (int j = 0; j < 8; j++) a[j] = As[k * 65 + tm * 8 + j];
#pragma unroll
        for (int j = 0; j < 8; j++) bv[j] = Bs[k * 257 + tn * 8 + j];
#pragma unroll
        for (int i = 0; i < 8; i++)
#pragma unroll
            for (int j = 0; j < 8; j++) acc[i][j] += a[i] * bv[j];
    }

#pragma unroll
    for (int j = 0; j < 8; j++) {
        int n = tn * 8 + j;
        float bias = bih[n] + bhh[n];
#pragma unroll
        for (int i = 0; i < 8; i++)
            g_buf[(size_t)(m0 + tm * 8 + i) * HH + n] = acc[i][j] + bias;
    }
}

// ---------------------------------------------------------------------------
// K3: in-place pre1: buf[m,n] = buf[m,:] . W_ih1[n,:] + b_ih1[n] + b_hh1[n]
// M = T*B, K = 256, N = 256. A tile fully staged to smem before overwrite,
// so the in-place update is race-free (each block touches only its own rows).
// ---------------------------------------------------------------------------
__global__ void __launch_bounds__(256)
pre1_kernel(const float* __restrict__ Wih, const float* __restrict__ bih,
            const float* __restrict__ bhh) {
    extern __shared__ float sm[];
    float* As = sm;               // [256 k][65 pad]
    float* Bs = sm + 256 * 65;    // [64 k][257 pad]
    const int tid = threadIdx.x;
    const int m0 = blockIdx.x * 64;

    for (int e = tid; e < 64 * 256; e += 256) {
        int r = e >> 8, k = e & 255;
        As[k * 65 + r] = g_buf[(size_t)(m0 + r) * HH + k];
    }

    const int tm = tid & 7;
    const int tn = tid >> 3;
    float acc[8][8];
#pragma unroll
    for (int i = 0; i < 8; i++)
#pragma unroll
        for (int j = 0; j < 8; j++) acc[i][j] = 0.f;

    for (int kc = 0; kc < 4; kc++) {
        const int k0 = kc * 64;
        __syncthreads();
        for (int e = tid; e < 64 * 256; e += 256) {
            int n = e >> 6, kk = e & 63;
            Bs[kk * 257 + n] = Wih[n * HH + k0 + kk];
        }
        __syncthreads();
#pragma unroll 8
        for (int kk = 0; kk < 64; kk++) {
            float a[8], bv[8];
#pragma unroll
            for (int j = 0; j < 8; j++) a[j] = As[(k0 + kk) * 65 + tm * 8 + j];
#pragma unroll
            for (int j = 0; j < 8; j++) bv[j] = Bs[kk * 257 + tn * 8 + j];
#pragma unroll
            for (int i = 0; i < 8; i++)
#pragma unroll
                for (int j = 0; j < 8; j++) acc[i][j] += a[i] * bv[j];
        }
    }

#pragma unroll
    for (int j = 0; j < 8; j++) {
        int n = tn * 8 + j;
        float bias = bih[n] + bhh[n];
#pragma unroll
        for (int i = 0; i < 8; i++)
            g_buf[(size_t)(m0 + tm * 8 + i) * HH + n] = acc[i][j] + bias;
    }
}

// ---------------------------------------------------------------------------
// K2: recurrence. Cluster of 2 CTAs, NB batches per cluster (64 clusters =
// 128 CTAs = one wave). CTA rank c owns k-slice [c*128, c*128+128). Thread t
// computes output row n = t over the local k-slice with W_hh[n][slice] held in
// 128 registers (zero weight traffic per step). Cross-slice partial sums are
// exchanged via DSMEM (double-buffered), one cluster barrier per step.
// h state: CTA c keeps h[k] for its own k-slice in smem — exactly the n-range
// its "own" threads finalize, so the update is local.
// ---------------------------------------------------------------------------
__global__ void __cluster_dims__(2, 1, 1) __launch_bounds__(256, 1)
rec_kernel(const float* __restrict__ Whh, const float* __restrict__ h0,
           float* __restrict__ hT) {
    __shared__ __align__(16) float h_sm[NB][128];
    __shared__ float ex[2][NB][128];
    const int tid = threadIdx.x;
    const int rank = blockIdx.x & 1;
    const int b0 = (blockIdx.x >> 1) * NB;
    const int kbase = rank * 128;
    const int n = tid;
    const bool own = ((n >> 7) == rank);
    const int nl = n & 127;

    float W[128];
#pragma unroll
    for (int k = 0; k < 128; k++) W[k] = Whh[n * HH + kbase + k];

    for (int idx = tid; idx < NB * 128; idx += 256) {
        int b = idx >> 7, j = idx & 127;
        h_sm[b][j] = h0[(b0 + b) * HH + kbase + j];
    }

    uint32_t ex_local = (uint32_t)__cvta_generic_to_shared(&ex[0][0][0]);
    uint32_t ex_peer;
    asm("mapa.shared::cluster.u32 %0, %1, %2;"
        : "=r"(ex_peer) : "r"(ex_local), "r"(rank ^ 1));

    asm volatile("barrier.cluster.arrive.aligned;\n" ::: "memory");
    asm volatile("barrier.cluster.wait.aligned;\n" ::: "memory");

    for (int t = 0; t < TT; t++) {
        // prefetch pre-activation for the finalize phase (overlaps FMA block)
        float pr[NB];
        if (own) {
#pragma unroll
            for (int b = 0; b < NB; b++)
                pr[b] = g_buf[((size_t)t * BB + b0 + b) * HH + n];
        }

        float acc[NB];
#pragma unroll
        for (int b = 0; b < NB; b++) acc[b] = 0.f;
#pragma unroll
        for (int kq = 0; kq < 32; kq++) {
#pragma unroll
            for (int b = 0; b < NB; b++) {
                float4 hv = *(const float4*)&h_sm[b][kq * 4];
                acc[b] += hv.x * W[kq * 4 + 0];
                acc[b] += hv.y * W[kq * 4 + 1];
                acc[b] += hv.z * W[kq * 4 + 2];
                acc[b] += hv.w * W[kq * 4 + 3];
            }
        }

        const int p = t & 1;
        if (!own) {
            uint32_t a = ex_peer + (uint32_t)(((p * NB) * 128 + nl) * 4);
#pragma unroll
            for (int b = 0; b < NB; b++)
                asm volatile("st.shared::cluster.f32 [%0], %1;"
                             :: "r"(a + (uint32_t)(b * 128 * 4)), "f"(acc[b])
                             : "memory");
        }
        // arrive has release semantics (orders the DSMEM stores); wait acquires.
        asm volatile("barrier.cluster.arrive.aligned;\n" ::: "memory");
        asm volatile("barrier.cluster.wait.aligned;\n" ::: "memory");

        if (own) {
#pragma unroll
            for (int b = 0; b < NB; b++) {
                float v = tanhf(pr[b] + acc[b] + ex[p][b][nl]);
                h_sm[b][nl] = v;
                g_buf[((size_t)t * BB + b0 + b) * HH + n] = v;
            }
        }
        __syncthreads();  // h_sm writes visible to whole CTA before next step
    }

    if (own) {
#pragma unroll
        for (int b = 0; b < NB; b++)
            hT[(b0 + b) * HH + n] = h_sm[b][nl];
    }
}

// ---------------------------------------------------------------------------
// K4: fc over the last F timesteps:
// out[b,f,o] = ys1[T-F+f, b, :] . fc_W[o,:] + fc_b[o]
// ---------------------------------------------------------------------------
__global__ void __launch_bounds__(256)
fc_kernel(const float* __restrict__ Wfc, const float* __restrict__ bfc,
          float* __restrict__ out) {
    __shared__ __align__(16) float xs[FF][HH];
    const int b = blockIdx.x;
    const int tid = threadIdx.x;
    for (int idx = tid; idx < FF * HH; idx += 256) {
        int f = idx >> 8, h = idx & 255;
        int t = TT - FF + f;
        xs[f][h] = g_buf[((size_t)t * BB + b) * HH + h];
    }
    __syncthreads();
    for (int fo = tid; fo < FF * OO; fo += 256) {
        int f = fo >> 6, o = fo & 63;
        float s = 0.f;
        const float4* wr = (const float4*)(Wfc + (size_t)o * HH);
        const float4* xr = (const float4*)&xs[f][0];
#pragma unroll
        for (int q = 0; q < 64; q++) {
            float4 w = wr[q], xv = xr[q];
            s += w.x * xv.x + w.y * xv.y + w.z * xv.z + w.w * xv.w;
        }
        out[((size_t)b * FF + f) * OO + o] = s + bfc[o];
    }
}

// ---------------------------------------------------------------------------
extern "C" void kernel_launch(void* const* d_in, const int* in_sizes, int n_in,
                              void* d_out, int out_size) {
    const float* x      = (const float*)d_in[0];
    const float* hidden = (const float*)d_in[1];
    const float* W_ih0  = (const float*)d_in[2];
    const float* W_hh0  = (const float*)d_in[3];
    const float* b_ih0  = (const float*)d_in[4];
    const float* b_hh0  = (const float*)d_in[5];
    const float* W_ih1  = (const float*)d_in[6];
    const float* W_hh1  = (const float*)d_in[7];
    const float* b_ih1  = (const float*)d_in[8];
    const float* b_hh1  = (const float*)d_in[9];
    const float* fc_W   = (const float*)d_in[10];
    const float* fc_b   = (const float*)d_in[11];

    float* out = (float*)d_out;                 // [B, F, O]
    float* hT  = out + (size_t)BB * FF * OO;    // [2, B, H] (second tuple element)

    const int sm1 = (64 * 65 + 64 * 257) * 4;
    const int sm3 = (256 * 65 + 64 * 257) * 4;
    cudaFuncSetAttribute(pre0_kernel, cudaFuncAttributeMaxDynamicSharedMemorySize, sm1);
    cudaFuncSetAttribute(pre1_kernel, cudaFuncAttributeMaxDynamicSharedMemorySize, sm3);

    const int mblocks = TT * BB / 64;  // 8192

    pre0_kernel<<<mblocks, 256, sm1>>>(x, W_ih0, b_ih0, b_hh0);
    rec_kernel<<<2 * (BB / NB), 256>>>(W_hh0, hidden, hT);
    pre1_kernel<<<mblocks, 256, sm3>>>(W_ih1, b_ih1, b_hh1);
    rec_kernel<<<2 * (BB / NB), 256>>>(W_hh1, hidden + (size_t)BB * HH,
                                       hT + (size_t)BB * HH);
    fc_kernel<<<BB, 256>>>(fc_W, fc_b, out);
}

// round 5
// speedup vs baseline: 1.0414x; 1.0414x over previous
#include <cuda_runtime.h>
#include <cuda_bf16.h>
#include <cstdint>
#include <cstddef>

#define BB 256
#define TT 2048
#define II 64
#define HH 256
#define OO 64
#define FF 16
#define NB 4   // batches per cluster in the recurrence kernel

typedef unsigned long long ull;

// ---- packed f32x2 helpers (sm_103a dual-fp32 path; ptxas never emits these
// from plain C++, only via PTX) -------------------------------------------
__device__ __forceinline__ ull pk2(float x, float y) {
    ull r; asm("mov.b64 %0, {%1, %2};" : "=l"(r) : "f"(x), "f"(y)); return r;
}
__device__ __forceinline__ void f2fma(ull& d, ull a, ull b) {
    asm("fma.rn.f32x2 %0, %1, %2, %0;" : "+l"(d) : "l"(a), "l"(b));
}
__device__ __forceinline__ float2 up2(ull v) {
    float2 f; asm("mov.b64 {%0, %1}, %2;" : "=f"(f.x), "=f"(f.y) : "l"(v)); return f;
}

// 512 MB scratch, reused in place: pre0 -> ys0 -> pre1 -> ys1. Layout [t][b][h].
__device__ float g_buf[(size_t)TT * BB * HH];

#define ASTR 68    // As row stride (k-major): 68 % 32 == 4 -> 16B-aligned, low conflict
#define BSTR 260   // Bs row stride: 260 % 4 == 0 -> 16B-aligned pair loads

// ---------------------------------------------------------------------------
// K1: pre0[t,b,n] = x[b,t,:] . W_ih0[n,:] + b_ih0[n] + b_hh0[n]
// M = T*B (m = t*256+b), K = 64, N = 256. 64x256 tile, 256 threads.
// f32x2: lanes pair over consecutive n (A operand duplicated per row).
// ---------------------------------------------------------------------------
__global__ void __launch_bounds__(256)
pre0_kernel(const float* __restrict__ x, const float* __restrict__ Wih,
            const float* __restrict__ bih, const float* __restrict__ bhh) {
    extern __shared__ float sm[];
    float* As = sm;                 // [64 k][ASTR] (m-contiguous)
    float* Bs = sm + 64 * ASTR;     // [64 k][BSTR] (n-contiguous)
    const int tid = threadIdx.x;
    const int m0 = blockIdx.x * 64;

    for (int e = tid; e < 64 * 64; e += 256) {
        int r = e >> 6, k = e & 63;
        int m = m0 + r;
        int b = m & (BB - 1);
        int t = m >> 8;
        As[k * ASTR + r] = x[((size_t)b * TT + t) * II + k];
    }
    for (int e = tid; e < 64 * 256; e += 256) {
        int n = e >> 6, k = e & 63;
        Bs[k * BSTR + n] = Wih[n * II + k];
    }
    __syncthreads();

    const int tm = tid & 7;
    const int tn = tid >> 3;
    ull acc2[8][4];
#pragma unroll
    for (int i = 0; i < 8; i++)
#pragma unroll
        for (int j = 0; j < 4; j++) acc2[i][j] = 0ull;

#pragma unroll 8
    for (int k = 0; k < 64; k++) {
        const float4* ar = (const float4*)&As[k * ASTR + tm * 8];
        float4 a0 = ar[0], a1 = ar[1];
        const ulonglong2* br = (const ulonglong2*)&Bs[k * BSTR + tn * 8];
        ulonglong2 q0 = br[0], q1 = br[1];
        ull b2[4] = {q0.x, q0.y, q1.x, q1.y};
        float a[8] = {a0.x, a0.y, a0.z, a0.w, a1.x, a1.y, a1.z, a1.w};
#pragma unroll
        for (int i = 0; i < 8; i++) {
            ull ad = pk2(a[i], a[i]);
#pragma unroll
            for (int j = 0; j < 4; j++) f2fma(acc2[i][j], ad, b2[j]);
        }
    }

#pragma unroll
    for (int j = 0; j < 4; j++) {
        int n0 = tn * 8 + 2 * j;
        float bias0 = bih[n0] + bhh[n0];
        float bias1 = bih[n0 + 1] + bhh[n0 + 1];
#pragma unroll
        for (int i = 0; i < 8; i++) {
            float2 v = up2(acc2[i][j]);
            size_t row = (size_t)(m0 + tm * 8 + i) * HH;
            g_buf[row + n0]     = v.x + bias0;
            g_buf[row + n0 + 1] = v.y + bias1;
        }
    }
}

// ---------------------------------------------------------------------------
// K3: in-place pre1: buf[m,n] = buf[m,:] . W_ih1[n,:] + b_ih1[n] + b_hh1[n]
// M = T*B, K = 256 (4 chunks of 64), N = 256. A staged fully before overwrite.
// ---------------------------------------------------------------------------
__global__ void __launch_bounds__(256)
pre1_kernel(const float* __restrict__ Wih, const float* __restrict__ bih,
            const float* __restrict__ bhh) {
    extern __shared__ float sm[];
    float* As = sm;                    // [256 k][ASTR]
    float* Bs = sm + 256 * ASTR;       // [64 k][BSTR]
    const int tid = threadIdx.x;
    const int m0 = blockIdx.x * 64;

    for (int e = tid; e < 64 * 256; e += 256) {
        int r = e >> 8, k = e & 255;
        As[k * ASTR + r] = g_buf[(size_t)(m0 + r) * HH + k];
    }

    const int tm = tid & 7;
    const int tn = tid >> 3;
    ull acc2[8][4];
#pragma unroll
    for (int i = 0; i < 8; i++)
#pragma unroll
        for (int j = 0; j < 4; j++) acc2[i][j] = 0ull;

    for (int kc = 0; kc < 4; kc++) {
        const int k0 = kc * 64;
        __syncthreads();
        for (int e = tid; e < 64 * 256; e += 256) {
            int n = e >> 6, kk = e & 63;
            Bs[kk * BSTR + n] = Wih[n * HH + k0 + kk];
        }
        __syncthreads();
#pragma unroll 8
        for (int kk = 0; kk < 64; kk++) {
            const float4* ar = (const float4*)&As[(k0 + kk) * ASTR + tm * 8];
            float4 a0 = ar[0], a1 = ar[1];
            const ulonglong2* br = (const ulonglong2*)&Bs[kk * BSTR + tn * 8];
            ulonglong2 q0 = br[0], q1 = br[1];
            ull b2[4] = {q0.x, q0.y, q1.x, q1.y};
            float a[8] = {a0.x, a0.y, a0.z, a0.w, a1.x, a1.y, a1.z, a1.w};
#pragma unroll
            for (int i = 0; i < 8; i++) {
                ull ad = pk2(a[i], a[i]);
#pragma unroll
                for (int j = 0; j < 4; j++) f2fma(acc2[i][j], ad, b2[j]);
            }
        }
    }

#pragma unroll
    for (int j = 0; j < 4; j++) {
        int n0 = tn * 8 + 2 * j;
        float bias0 = bih[n0] + bhh[n0];
        float bias1 = bih[n0 + 1] + bhh[n0 + 1];
#pragma unroll
        for (int i = 0; i < 8; i++) {
            float2 v = up2(acc2[i][j]);
            size_t row = (size_t)(m0 + tm * 8 + i) * HH;
            g_buf[row + n0]     = v.x + bias0;
            g_buf[row + n0 + 1] = v.y + bias1;
        }
    }
}

// ---------------------------------------------------------------------------
// K2: recurrence. Cluster of 2 CTAs, NB batches per cluster (64 clusters =
// 128 CTAs = one wave). CTA rank c owns k-slice [c*128, c*128+128). Thread t
// computes output row n = t over the local k-slice; W_hh[n][slice] lives in
// 64 x 64-bit registers as (even-k, odd-k) pairs. Inner product uses
// fma.rn.f32x2 with lanes accumulating even/odd k; one horizontal add per
// step. Cross-slice partials exchanged via DSMEM (double-buffered), one
// cluster barrier per step.
// ---------------------------------------------------------------------------
__global__ void __cluster_dims__(2, 1, 1) __launch_bounds__(256, 1)
rec_kernel(const float* __restrict__ Whh, const float* __restrict__ h0,
           float* __restrict__ hT) {
    __shared__ __align__(16) float h_sm[NB][128];
    __shared__ float ex[2][NB][128];
    const int tid = threadIdx.x;
    const int rank = blockIdx.x & 1;
    const int b0 = (blockIdx.x >> 1) * NB;
    const int kbase = rank * 128;
    const int n = tid;
    const bool own = ((n >> 7) == rank);
    const int nl = n & 127;

    // W pairs: W2[j] = (W[2j], W[2j+1]) over the local k-slice. 16B-aligned.
    ull W2[64];
    {
        const ulonglong2* wp = (const ulonglong2*)(Whh + (size_t)n * HH + kbase);
#pragma unroll
        for (int q = 0; q < 32; q++) {
            ulonglong2 v = wp[q];
            W2[2 * q]     = v.x;
            W2[2 * q + 1] = v.y;
        }
    }

    for (int idx = tid; idx < NB * 128; idx += 256) {
        int b = idx >> 7, j = idx & 127;
        h_sm[b][j] = h0[(b0 + b) * HH + kbase + j];
    }

    uint32_t ex_local = (uint32_t)__cvta_generic_to_shared(&ex[0][0][0]);
    uint32_t ex_peer;
    asm("mapa.shared::cluster.u32 %0, %1, %2;"
        : "=r"(ex_peer) : "r"(ex_local), "r"(rank ^ 1));

    asm volatile("barrier.cluster.arrive.aligned;\n" ::: "memory");
    asm volatile("barrier.cluster.wait.aligned;\n" ::: "memory");

    for (int t = 0; t < TT; t++) {
        // prefetch pre-activation early (LDG latency overlaps the FMA block)
        float pr[NB];
        if (own) {
#pragma unroll
            for (int b = 0; b < NB; b++)
                pr[b] = g_buf[((size_t)t * BB + b0 + b) * HH + n];
        }

        ull acc2[NB];
#pragma unroll
        for (int b = 0; b < NB; b++) acc2[b] = 0ull;
#pragma unroll
        for (int kq = 0; kq < 32; kq++) {
#pragma unroll
            for (int b = 0; b < NB; b++) {
                ulonglong2 hv = *(const ulonglong2*)&h_sm[b][kq * 4];
                f2fma(acc2[b], hv.x, W2[2 * kq]);
                f2fma(acc2[b], hv.y, W2[2 * kq + 1]);
            }
        }
        float s[NB];
#pragma unroll
        for (int b = 0; b < NB; b++) {
            float2 v = up2(acc2[b]);
            s[b] = v.x + v.y;
        }

        const int p = t & 1;
        if (!own) {
            uint32_t a = ex_peer + (uint32_t)(((p * NB) * 128 + nl) * 4);
#pragma unroll
            for (int b = 0; b < NB; b++)
                asm volatile("st.shared::cluster.f32 [%0], %1;"
                             :: "r"(a + (uint32_t)(b * 128 * 4)), "f"(s[b])
                             : "memory");
        }
        // arrive releases the DSMEM stores; wait acquires the peer's.
        asm volatile("barrier.cluster.arrive.aligned;\n" ::: "memory");
        asm volatile("barrier.cluster.wait.aligned;\n" ::: "memory");

        if (own) {
#pragma unroll
            for (int b = 0; b < NB; b++) {
                float v = tanhf(pr[b] + s[b] + ex[p][b][nl]);
                h_sm[b][nl] = v;
                g_buf[((size_t)t * BB + b0 + b) * HH + n] = v;
            }
        }
        __syncthreads();  // h_sm writes visible CTA-wide before next step
    }

    if (own) {
#pragma unroll
        for (int b = 0; b < NB; b++)
            hT[(b0 + b) * HH + n] = h_sm[b][nl];
    }
}

// ---------------------------------------------------------------------------
// K4: fc over the last F timesteps:
// out[b,f,o] = ys1[T-F+f, b, :] . fc_W[o,:] + fc_b[o]
// ---------------------------------------------------------------------------
__global__ void __launch_bounds__(256)
fc_kernel(const float* __restrict__ Wfc, const float* __restrict__ bfc,
          float* __restrict__ out) {
    __shared__ __align__(16) float xs[FF][HH];
    const int b = blockIdx.x;
    const int tid = threadIdx.x;
    for (int idx = tid; idx < FF * HH; idx += 256) {
        int f = idx >> 8, h = idx & 255;
        int t = TT - FF + f;
        xs[f][h] = g_buf[((size_t)t * BB + b) * HH + h];
    }
    __syncthreads();
    for (int fo = tid; fo < FF * OO; fo += 256) {
        int f = fo >> 6, o = fo & 63;
        float s = 0.f;
        const float4* wr = (const float4*)(Wfc + (size_t)o * HH);
        const float4* xr = (const float4*)&xs[f][0];
#pragma unroll
        for (int q = 0; q < 64; q++) {
            float4 w = wr[q], xv = xr[q];
            s += w.x * xv.x + w.y * xv.y + w.z * xv.z + w.w * xv.w;
        }
        out[((size_t)b * FF + f) * OO + o] = s + bfc[o];
    }
}

// ---------------------------------------------------------------------------
extern "C" void kernel_launch(void* const* d_in, const int* in_sizes, int n_in,
                              void* d_out, int out_size) {
    const float* x      = (const float*)d_in[0];
    const float* hidden = (const float*)d_in[1];
    const float* W_ih0  = (const float*)d_in[2];
    const float* W_hh0  = (const float*)d_in[3];
    const float* b_ih0  = (const float*)d_in[4];
    const float* b_hh0  = (const float*)d_in[5];
    const float* W_ih1  = (const float*)d_in[6];
    const float* W_hh1  = (const float*)d_in[7];
    const float* b_ih1  = (const float*)d_in[8];
    const float* b_hh1  = (const float*)d_in[9];
    const float* fc_W   = (const float*)d_in[10];
    const float* fc_b   = (const float*)d_in[11];

    float* out = (float*)d_out;                 // [B, F, O]
    float* hT  = out + (size_t)BB * FF * OO;    // [2, B, H]

    const int sm1 = (64 * ASTR + 64 * BSTR) * 4;    // pre0:  ~83 KB
    const int sm3 = (256 * ASTR + 64 * BSTR) * 4;   // pre1: ~133 KB
    cudaFuncSetAttribute(pre0_kernel, cudaFuncAttributeMaxDynamicSharedMemorySize, sm1);
    cudaFuncSetAttribute(pre1_kernel, cudaFuncAttributeMaxDynamicSharedMemorySize, sm3);

    const int mblocks = TT * BB / 64;  // 8192

    pre0_kernel<<<mblocks, 256, sm1>>>(x, W_ih0, b_ih0, b_hh0);
    rec_kernel<<<2 * (BB / NB), 256>>>(W_hh0, hidden, hT);
    pre1_kernel<<<mblocks, 256, sm3>>>(W_ih1, b_ih1, b_hh1);
    rec_kernel<<<2 * (BB / NB), 256>>>(W_hh1, hidden + (size_t)BB * HH,
                                       hT + (size_t)BB * HH);
    fc_kernel<<<BB, 256>>>(fc_W, fc_b, out);
}